// round 2
// baseline (speedup 1.0000x reference)
#include <cuda_runtime.h>
#include <cstdint>

// LSTM scan, persistent 8-CTA-cluster kernel, tf32 mma.sync.
// T=2048 steps, B=256 batch, E=128, H=256 (4H=1024 gate rows).
//
// Decomposition:
//   16 clusters x 8 CTAs = 128 CTAs (1 per SM, 223KB smem each).
//   Cluster c owns batch rows [16c, 16c+16).  CTA rank r in the cluster owns
//   hidden units [32r, 32r+32) -> gate rows {g*256 + 32r + j} for g in i,f,g,o.
//   W chunk [128 rows x 384 K] (K = h(256) || x(128)) lives in smem in
//   pre-swizzled tf32 mma B-fragment order for the whole run.
//   Per step: stage A=[16,384] fragments (h from L2 exchange buf + emb gather),
//   4 warps run m16n8k8 tf32 mma over 48 k-tiles, elementwise gate math on the
//   owned 32-unit chunk, publish h chunk to a double-buffered __device__ array,
//   one cluster.sync per step.

#define T_STEPS 2048
#define BATCH   256
#define EDIM    128
#define HDIM    256
#define CLSZ    8
#define NCLUST  16
#define BC      16
#define JCH     32
#define LROWS   128
#define KTOT    384
#define NKT     48
#define NNT     16
#define NTHR    256

// h exchange buffer, double buffered: [buf][cluster][batch][hidden]
__device__ float g_hbuf[2][NCLUST][BC][HDIM];

__device__ __forceinline__ uint32_t f2tf(float x) {
    uint32_t u;
    asm("cvt.rna.tf32.f32 %0, %1;" : "=r"(u) : "f"(x));
    return u;
}
__device__ __forceinline__ float sigf(float x) { return 1.0f / (1.0f + __expf(-x)); }
__device__ __forceinline__ float tanh_fast(float x) { return 2.0f * sigf(2.0f * x) - 1.0f; }
__device__ __forceinline__ void cluster_sync_all() {
    asm volatile("barrier.cluster.arrive.aligned;\n\tbarrier.cluster.wait.aligned;\n" ::: "memory");
}
__device__ __forceinline__ void mma_tf32(float d[4], uint32_t a0, uint32_t a1, uint32_t a2,
                                         uint32_t a3, uint32_t b0, uint32_t b1) {
    asm volatile(
        "mma.sync.aligned.m16n8k8.row.col.f32.tf32.tf32.f32 "
        "{%0,%1,%2,%3},{%4,%5,%6,%7},{%8,%9},{%0,%1,%2,%3};"
        : "+f"(d[0]), "+f"(d[1]), "+f"(d[2]), "+f"(d[3])
        : "r"(a0), "r"(a1), "r"(a2), "r"(a3), "r"(b0), "r"(b1));
}

extern __shared__ uint32_t smem_u[];
// 32-bit word layout:
//   [0, 49152)      W fragments (uint2 pairs, tf32)          196608 B
//   [49152, 55296)  A fragments (tf32); overlaid by gates     24576 B
//   [55296, 55808)  c state (float [16][32])                   2048 B
//   [55808, 55936)  bias (float [128])                          512 B
#define SMEM_WORDS 55936

__global__ void __cluster_dims__(CLSZ, 1, 1) __launch_bounds__(NTHR, 1)
lstm_kernel(const int* __restrict__ inputs, const float* __restrict__ emb,
            const float* __restrict__ Wih, const float* __restrict__ Whh,
            const float* __restrict__ bih, const float* __restrict__ bhh,
            const float* __restrict__ Wout, const float* __restrict__ bout,
            float* __restrict__ out)
{
    const int tid  = threadIdx.x;
    const int lane = tid & 31;
    const int wid  = tid >> 5;
    const int rank = blockIdx.x & (CLSZ - 1);
    const int cl   = blockIdx.x >> 3;

    uint2*    wf     = (uint2*)smem_u;
    uint32_t* af     = smem_u + 49152;
    float*    gates  = (float*)af;              // overlay (A dead when gates live)
    float*    c_s    = (float*)(smem_u + 55296);
    float*    bias_s = (float*)(smem_u + 55808);

    // ---- one-time init: W chunk -> B-fragment order (tf32) ----
    // wf[((nt*NKT)+kt)*32 + lane] = { W(nloc, k0), W(nloc, k0+4) }
    //   nloc = nt*8 + (lane>>2), k0 = kt*8 + (lane&3)
    for (int idx = tid; idx < NNT * NKT * 32; idx += NTHR) {
        int l    = idx & 31;
        int kt   = (idx >> 5) % NKT;
        int nt   = idx / (32 * NKT);
        int nloc = nt * 8 + (l >> 2);
        int R    = ((nloc >> 5) << 8) + rank * JCH + (nloc & 31);  // global gate row
        int k0   = kt * 8 + (l & 3);
        int k1   = k0 + 4;
        float w0 = (k0 < HDIM) ? Whh[R * HDIM + k0] : Wih[R * EDIM + (k0 - HDIM)];
        float w1 = (k1 < HDIM) ? Whh[R * HDIM + k1] : Wih[R * EDIM + (k1 - HDIM)];
        wf[idx] = make_uint2(f2tf(w0), f2tf(w1));
    }
    if (tid < LROWS) {
        int R = ((tid >> 5) << 8) + rank * JCH + (tid & 31);
        bias_s[tid] = bih[R] + bhh[R];
    }
    for (int p = tid; p < BC * JCH; p += NTHR) c_s[p] = 0.0f;
    __syncthreads();

    // ---- scan ----
    for (int t = 0; t < T_STEPS; ++t) {
        // Stage A fragments: A[row=batch 0..15][col 0..383], col<256 -> h, else emb
        const float* hb = &g_hbuf[t & 1][cl][0][0];
        for (int i = tid; i < BC * KTOT; i += NTHR) {
            int row = i / KTOT;
            int col = i - row * KTOT;
            float v;
            if (col < HDIM) {
                v = (t == 0) ? 0.0f : __ldcg(hb + row * HDIM + col);
            } else {
                int tok = __ldg(&inputs[t * BATCH + cl * BC + row]);
                v = __ldg(&emb[(long long)tok * EDIM + (col - HDIM)]);
            }
            int kt   = col >> 3, c3 = col & 7;
            int fl   = ((row & 7) << 2) | (c3 & 3);
            int slot = (row >> 3) | ((c3 >> 2) << 1);
            af[(kt * 32 + fl) * 4 + slot] = f2tf(v);
        }
        __syncthreads();

        // GEMM: 4 warps, warp w owns n-tiles [4w, 4w+4) (32 gate rows)
        float acc[4][4];
        if (wid < 4) {
            #pragma unroll
            for (int n4 = 0; n4 < 4; ++n4) {
                int n0 = (wid * 4 + n4) * 8 + ((lane & 3) << 1);
                acc[n4][0] = bias_s[n0];
                acc[n4][1] = bias_s[n0 + 1];
                acc[n4][2] = bias_s[n0];
                acc[n4][3] = bias_s[n0 + 1];
            }
            #pragma unroll 4
            for (int kt = 0; kt < NKT; ++kt) {
                uint4 a = *(const uint4*)(af + (kt * 32 + lane) * 4);
                #pragma unroll
                for (int n4 = 0; n4 < 4; ++n4) {
                    uint2 b = wf[((wid * 4 + n4) * NKT + kt) * 32 + lane];
                    mma_tf32(acc[n4], a.x, a.y, a.z, a.w, b.x, b.y);
                }
            }
        }
        __syncthreads();  // all A-fragment reads done before gates overlay

        if (wid < 4) {
            int r = lane >> 2;
            #pragma unroll
            for (int n4 = 0; n4 < 4; ++n4) {
                int n0 = (wid * 4 + n4) * 8 + ((lane & 3) << 1);
                *(float2*)(gates + r * LROWS + n0)       = make_float2(acc[n4][0], acc[n4][1]);
                *(float2*)(gates + (r + 8) * LROWS + n0) = make_float2(acc[n4][2], acc[n4][3]);
            }
        }
        __syncthreads();

        // Elementwise LSTM cell on owned chunk; publish h
        float* hw = &g_hbuf[(t + 1) & 1][cl][0][0];
        for (int p = tid; p < BC * JCH; p += NTHR) {
            int b = p >> 5, jj = p & 31;
            float gi = sigf(gates[b * LROWS + jj]);
            float gf = sigf(gates[b * LROWS + 32 + jj]);
            float gg = tanh_fast(gates[b * LROWS + 64 + jj]);
            float go = sigf(gates[b * LROWS + 96 + jj]);
            float c  = gf * c_s[p] + gi * gg;
            c_s[p]   = c;
            float h  = go * tanh_fast(c);
            hw[b * HDIM + rank * JCH + jj] = h;
        }
        __threadfence();       // make h chunk visible at GPU scope
        cluster_sync_all();    // one barrier per step (double-buffered exchange)
    }

    // ---- head: y[b] = sigmoid(h_T[b] . Wout + bout), rank-0 CTA per cluster ----
    if (rank == 0 && tid < BC) {
        float s = bout[0];
        const float* hb = &g_hbuf[0][cl][tid][0];  // T even -> final h in buf 0
        #pragma unroll 8
        for (int j = 0; j < HDIM; ++j) s += __ldcg(hb + j) * Wout[j];
        out[cl * BC + tid] = sigf(s);
    }
}

extern "C" void kernel_launch(void* const* d_in, const int* in_sizes, int n_in,
                              void* d_out, int out_size)
{
    (void)in_sizes; (void)n_in; (void)out_size;
    cudaFuncSetAttribute(lstm_kernel, cudaFuncAttributeMaxDynamicSharedMemorySize,
                         SMEM_WORDS * 4);
    lstm_kernel<<<NCLUST * CLSZ, NTHR, SMEM_WORDS * 4>>>(
        (const int*)d_in[0], (const float*)d_in[1], (const float*)d_in[2],
        (const float*)d_in[3], (const float*)d_in[4], (const float*)d_in[5],
        (const float*)d_in[6], (const float*)d_in[7], (float*)d_out);
}

// round 3
// speedup vs baseline: 2.4684x; 2.4684x over previous
#include <cuda_runtime.h>
#include <cuda_bf16.h>
#include <cstdint>

// Persistent 8-CTA-cluster LSTM scan, bf16 m16n8k16 mma, DSMEM h exchange.
// T=2048, B=256, E=128, H=256 (4H=1024 gate rows).
//   16 clusters x 8 CTAs = 128 CTAs (1/SM). Cluster c: batch [16c,16c+16).
//   CTA rank r: hidden units [32r,32r+32) -> 128 gate rows. W chunk [128x384]
//   bf16 lives in smem in mma B-fragment order for the whole run.
// Per step: warps 0-3 mma over K=384 (24 k16-tiles) reading A-frag buffer t&1;
//   warps 4-7 stage next step's emb columns into buffer (t+1)&1; one
//   __syncthreads; all warps do gate math (c in registers) and push h (bf16x2,
//   fragment layout) to all 8 CTAs' next A buffer via st.shared::cluster;
//   one cluster.sync (release/acquire) per step. No global traffic in the loop.

#define T_STEPS 2048
#define BATCH   256
#define EDIM    128
#define HDIM    256
#define CLSZ    8
#define BC      16
#define NKT     24
#define NNT     16
#define NTHR    256
#define GSTRIDE 132   // padded gates row stride (words) to dodge bank conflicts

// smem word map
#define WF_W        0          // W fragments: 16*24*32 uint2 = 24576 words
#define AF_W        24576      // A fragments: 2 buffers x 3072 words
#define AF_STRIDE_W 3072
#define AF_STRIDE_B 12288
#define GA_W        30720      // gates: 16*132 = 2112 words
#define BI_W        32832      // bias: 128 words
#define SMEM_WORDS  32960      // 131840 bytes

extern __shared__ uint32_t smem_u[];

__device__ __forceinline__ uint32_t packbf(float lo, float hi) {
    uint32_t u;
    asm("cvt.rn.bf16x2.f32 %0, %1, %2;" : "=r"(u) : "f"(hi), "f"(lo));
    return u;
}
__device__ __forceinline__ float sigf(float x) { return 1.0f / (1.0f + __expf(-x)); }
__device__ __forceinline__ float tanh_fast(float x) { return 2.0f * sigf(2.0f * x) - 1.0f; }
__device__ __forceinline__ void csync() {
    asm volatile("barrier.cluster.arrive.aligned;" ::: "memory");
    asm volatile("barrier.cluster.wait.aligned;" ::: "memory");
}
__device__ __forceinline__ uint32_t smem_u32(const void* p) {
    uint32_t a;
    asm("{ .reg .u64 t; cvta.to.shared.u64 t, %1; cvt.u32.u64 %0, t; }" : "=r"(a) : "l"(p));
    return a;
}
__device__ __forceinline__ uint32_t mapa32(uint32_t a, uint32_t r) {
    uint32_t d;
    asm("mapa.shared::cluster.u32 %0, %1, %2;" : "=r"(d) : "r"(a), "r"(r));
    return d;
}
__device__ __forceinline__ void stc32(uint32_t a, uint32_t v) {
    asm volatile("st.shared::cluster.u32 [%0], %1;" :: "r"(a), "r"(v) : "memory");
}
__device__ __forceinline__ void mma16816(float d[4], uint32_t a0, uint32_t a1, uint32_t a2,
                                         uint32_t a3, uint32_t b0, uint32_t b1) {
    asm volatile(
        "mma.sync.aligned.m16n8k16.row.col.f32.bf16.bf16.f32 "
        "{%0,%1,%2,%3},{%4,%5,%6,%7},{%8,%9},{%0,%1,%2,%3};"
        : "+f"(d[0]), "+f"(d[1]), "+f"(d[2]), "+f"(d[3])
        : "r"(a0), "r"(a1), "r"(a2), "r"(a3), "r"(b0), "r"(b1));
}
// word offset (within one A buffer) of packed pair holding A[row=b][col,col+1], col even
__device__ __forceinline__ int afrag_word(int b, int col) {
    int kt = col >> 4, kk = col & 15;
    int t3 = (kk >> 1) & 3;
    int r  = ((b >> 3) & 1) | (((kk >> 3) & 1) << 1);
    int ln = (b & 7) * 4 + t3;
    return (kt * 32 + ln) * 4 + r;
}

__global__ void __cluster_dims__(CLSZ, 1, 1) __launch_bounds__(NTHR, 1)
lstm_kernel(const int* __restrict__ inputs, const float* __restrict__ emb,
            const float* __restrict__ Wih, const float* __restrict__ Whh,
            const float* __restrict__ bih, const float* __restrict__ bhh,
            const float* __restrict__ Wout, const float* __restrict__ bout,
            float* __restrict__ out)
{
    const int tid  = threadIdx.x;
    const int lane = tid & 31;
    const int wid  = tid >> 5;
    const int rank = blockIdx.x & (CLSZ - 1);
    const int cl   = blockIdx.x >> 3;

    uint2*    wf     = (uint2*)(smem_u + WF_W);
    uint32_t* af     = smem_u + AF_W;
    float*    gates  = (float*)(smem_u + GA_W);
    float*    bias_s = (float*)(smem_u + BI_W);

    // ---- one-time: W chunk -> bf16 B-fragment order ----
    for (int idx = tid; idx < NNT * NKT * 32; idx += NTHR) {
        int l  = idx & 31;
        int kt = (idx >> 5) % NKT;
        int nt = idx / (32 * NKT);
        int n  = nt * 8 + (l >> 2);
        int R  = ((n >> 5) << 8) + rank * 32 + (n & 31);
        int ka = kt * 16 + (l & 3) * 2;
        int kb = ka + 8;
        float w00 = (ka     < HDIM) ? Whh[R * HDIM + ka]     : Wih[R * EDIM + ka - HDIM];
        float w01 = (ka + 1 < HDIM) ? Whh[R * HDIM + ka + 1] : Wih[R * EDIM + ka + 1 - HDIM];
        float w10 = (kb     < HDIM) ? Whh[R * HDIM + kb]     : Wih[R * EDIM + kb - HDIM];
        float w11 = (kb + 1 < HDIM) ? Whh[R * HDIM + kb + 1] : Wih[R * EDIM + kb + 1 - HDIM];
        wf[idx] = make_uint2(packbf(w00, w01), packbf(w10, w11));
    }
    if (tid < 128) {
        int R = ((tid >> 5) << 8) + rank * 32 + (tid & 31);
        bias_s[tid] = bih[R] + bhh[R];
    }

    // ---- prologue: h(0)=0 into buf0; stage x(0) into buf0 ----
    for (int w = tid; w < 2048; w += NTHR) af[w] = 0u;
    for (int idx = tid; idx < 1024; idx += NTHR) {
        int b  = idx >> 6;
        int pi = idx & 63;
        int tok = __ldg(&inputs[cl * BC + b]);
        float2 e = *(const float2*)&emb[tok * EDIM + pi * 2];
        af[afrag_word(b, 256 + pi * 2)] = packbf(e.x, e.y);
    }

    // ---- per-thread constants ----
    uint32_t af_base = smem_u32(af);
    uint32_t remA[CLSZ];
    #pragma unroll
    for (uint32_t r = 0; r < CLSZ; ++r) remA[r] = mapa32(af_base, r);

    const int eb  = tid >> 4;             // owned batch row
    const int ejj = (tid & 15) * 2;       // owned hidden pair (within 32-chunk)
    const uint32_t pushByte = (uint32_t)afrag_word(eb, rank * 32 + ejj) * 4;
    const float* gp = gates + eb * GSTRIDE + ejj;
    float c0 = 0.0f, c1 = 0.0f;

    int sb = 0, scol0 = 0;
    int sword[8];
    if (wid >= 4) {                       // x-staging role
        int q0 = ((wid - 4) * 32 + lane) * 8;
        sb    = q0 >> 6;
        scol0 = (q0 & 63) * 2;
        #pragma unroll
        for (int s = 0; s < 8; ++s) sword[s] = afrag_word(sb, 256 + scol0 + s * 2);
    }
    __syncthreads();

    // ---- scan ----
    for (int t = 0; t < T_STEPS; ++t) {
        uint32_t* cur = af + (t & 1) * AF_STRIDE_W;
        uint32_t* nxt = af + ((t + 1) & 1) * AF_STRIDE_W;

        if (wid < 4) {
            float acc[4][4];
            #pragma unroll
            for (int n4 = 0; n4 < 4; ++n4) {
                int n0 = (wid * 4 + n4) * 8 + (lane & 3) * 2;
                float bv0 = bias_s[n0], bv1 = bias_s[n0 + 1];
                acc[n4][0] = bv0; acc[n4][1] = bv1; acc[n4][2] = bv0; acc[n4][3] = bv1;
            }
            #pragma unroll
            for (int kt = 0; kt < NKT; ++kt) {
                uint4 a = *(const uint4*)(cur + (kt * 32 + lane) * 4);
                #pragma unroll
                for (int n4 = 0; n4 < 4; ++n4) {
                    uint2 b = wf[((wid * 4 + n4) * NKT + kt) * 32 + lane];
                    mma16816(acc[n4], a.x, a.y, a.z, a.w, b.x, b.y);
                }
            }
            int r0 = lane >> 2;
            #pragma unroll
            for (int n4 = 0; n4 < 4; ++n4) {
                int n0 = (wid * 4 + n4) * 8 + (lane & 3) * 2;
                *(float2*)(gates + r0 * GSTRIDE + n0)       = make_float2(acc[n4][0], acc[n4][1]);
                *(float2*)(gates + (r0 + 8) * GSTRIDE + n0) = make_float2(acc[n4][2], acc[n4][3]);
            }
        } else if (t + 1 < T_STEPS) {
            int tok = __ldg(&inputs[(t + 1) * BATCH + cl * BC + sb]);
            const float* er = emb + tok * EDIM + scol0;
            #pragma unroll
            for (int s = 0; s < 8; ++s) {
                float2 e = *(const float2*)(er + s * 2);
                nxt[sword[s]] = packbf(e.x, e.y);
            }
        }
        __syncthreads();

        // gate math on owned pair; push h to all 8 CTAs' next A buffer
        float2 xi = *(const float2*)(gp);
        float2 xf = *(const float2*)(gp + 32);
        float2 xg = *(const float2*)(gp + 64);
        float2 xo = *(const float2*)(gp + 96);
        float i0 = sigf(xi.x), i1 = sigf(xi.y);
        float f0 = sigf(xf.x), f1 = sigf(xf.y);
        float g0 = tanh_fast(xg.x), g1 = tanh_fast(xg.y);
        float o0 = sigf(xo.x), o1 = sigf(xo.y);
        c0 = f0 * c0 + i0 * g0;
        c1 = f1 * c1 + i1 * g1;
        float h0 = o0 * tanh_fast(c0);
        float h1 = o1 * tanh_fast(c1);
        uint32_t hp   = packbf(h0, h1);
        uint32_t boff = (uint32_t)(((t + 1) & 1) * AF_STRIDE_B) + pushByte;
        #pragma unroll
        for (uint32_t r = 0; r < CLSZ; ++r) stc32(remA[r] + boff, hp);

        csync();   // release h pushes; acquire peers' pushes
    }

    // ---- head: h_T fully assembled in rank-0's A buffer 0 ----
    if (rank == 0 && tid < BC) {
        float s = __ldg(bout);
        int b = tid;
        #pragma unroll 8
        for (int j = 0; j < HDIM; j += 2) {
            uint32_t w = af[afrag_word(b, j)];
            float lo = __uint_as_float(w << 16);
            float hi = __uint_as_float(w & 0xFFFF0000u);
            s += lo * __ldg(&Wout[j]) + hi * __ldg(&Wout[j + 1]);
        }
        out[cl * BC + b] = sigf(s);
    }
}

extern "C" void kernel_launch(void* const* d_in, const int* in_sizes, int n_in,
                              void* d_out, int out_size)
{
    (void)in_sizes; (void)n_in; (void)out_size;
    cudaFuncSetAttribute(lstm_kernel, cudaFuncAttributeMaxDynamicSharedMemorySize,
                         SMEM_WORDS * 4);
    lstm_kernel<<<16 * CLSZ, NTHR, SMEM_WORDS * 4>>>(
        (const int*)d_in[0], (const float*)d_in[1], (const float*)d_in[2],
        (const float*)d_in[3], (const float*)d_in[4], (const float*)d_in[5],
        (const float*)d_in[6], (const float*)d_in[7], (float*)d_out);
}

// round 5
// speedup vs baseline: 5.1474x; 2.0853x over previous
#include <cuda_runtime.h>
#include <cuda_bf16.h>
#include <cstdint>

// Persistent 4-CTA-cluster LSTM scan, bf16 m16n8k16 HMMA, DSMEM h exchange,
// register-resident gates (gate-aligned n-tile assignment).
// T=2048, B=256, E=128, H=256 (4H=1024 gate rows).
//   16 clusters x 4 CTAs = 64 CTAs. Cluster cl: batch [16cl, 16cl+16).
//   CTA rank r: hidden units [64r, 64r+64) -> 256 local gate rows (4 gates x 64).
//   W chunk [256 x 384] bf16 in smem in mma B-fragment order, resident all run.
// Per step (all 8 warps):
//   - issue emb/token loads for x(t+1)
//   - mma: warp w computes n-tiles {w+8g : g=0..3} over 24 k16-tiles; the 4
//     accumulators of each thread are exactly (i,f,g,o) of one (batch,unit)
//     cell pair -> LSTM cell update entirely in registers (c in registers)
//   - store x(t+1) into next A buffer (local), push h(t+1) bf16x2 into all 4
//     CTAs' next A buffer via st.shared::cluster
//   - barrier.cluster.arrive ; barrier.cluster.wait   (one barrier per step)

#define T_STEPS 2048
#define BATCH   256
#define EDIM    128
#define HDIM    256
#define CLSZ    4
#define BC      16
#define NKT     24
#define NNT     32
#define NTHR    256

// smem word map
#define WF_W        0        // W fragments: 32 n-tiles x 24 kt x 32 lanes uint2 = 49152 words
#define AF_W        49152    // A fragments: 2 buffers x 3072 words
#define AF_STRIDE_W 3072
#define SMEM_WORDS  55296    // 221184 bytes

extern __shared__ uint32_t smem_u[];

__device__ __forceinline__ uint32_t packbf(float lo, float hi) {
    uint32_t u;
    asm("cvt.rn.bf16x2.f32 %0, %1, %2;" : "=r"(u) : "f"(hi), "f"(lo));
    return u;
}
__device__ __forceinline__ float tanha(float x) {
    float y;
    asm("tanh.approx.f32 %0, %1;" : "=f"(y) : "f"(x));
    return y;
}
__device__ __forceinline__ float sigf(float x) { return fmaf(0.5f, tanha(0.5f * x), 0.5f); }
__device__ __forceinline__ void carrive() {
    asm volatile("barrier.cluster.arrive.aligned;" ::: "memory");
}
__device__ __forceinline__ void cwait() {
    asm volatile("barrier.cluster.wait.aligned;" ::: "memory");
}
__device__ __forceinline__ uint32_t smem_u32(const void* p) {
    uint32_t a;
    asm("{ .reg .u64 t; cvta.to.shared.u64 t, %1; cvt.u32.u64 %0, t; }" : "=r"(a) : "l"(p));
    return a;
}
__device__ __forceinline__ uint32_t mapa32(uint32_t a, uint32_t r) {
    uint32_t d;
    asm("mapa.shared::cluster.u32 %0, %1, %2;" : "=r"(d) : "r"(a), "r"(r));
    return d;
}
__device__ __forceinline__ void stc32(uint32_t a, uint32_t v) {
    asm volatile("st.shared::cluster.u32 [%0], %1;" :: "r"(a), "r"(v) : "memory");
}
__device__ __forceinline__ void mma16816(float d[4], uint32_t a0, uint32_t a1, uint32_t a2,
                                         uint32_t a3, uint32_t b0, uint32_t b1) {
    asm volatile(
        "mma.sync.aligned.m16n8k16.row.col.f32.bf16.bf16.f32 "
        "{%0,%1,%2,%3},{%4,%5,%6,%7},{%8,%9},{%0,%1,%2,%3};"
        : "+f"(d[0]), "+f"(d[1]), "+f"(d[2]), "+f"(d[3])
        : "r"(a0), "r"(a1), "r"(a2), "r"(a3), "r"(b0), "r"(b1));
}
// word offset (within one A buffer) of the packed pair holding A[row=b][col,col+1], col even
__device__ __forceinline__ int afrag_word(int b, int col) {
    int kt = col >> 4, kk = col & 15;
    int t3 = (kk >> 1) & 3;
    int r  = ((b >> 3) & 1) | (((kk >> 3) & 1) << 1);
    int ln = (b & 7) * 4 + t3;
    return (kt * 32 + ln) * 4 + r;
}

__global__ void __cluster_dims__(CLSZ, 1, 1) __launch_bounds__(NTHR, 1)
lstm_kernel(const int* __restrict__ inputs, const float* __restrict__ emb,
            const float* __restrict__ Wih, const float* __restrict__ Whh,
            const float* __restrict__ bih, const float* __restrict__ bhh,
            const float* __restrict__ Wout, const float* __restrict__ bout,
            float* __restrict__ out)
{
    const int tid  = threadIdx.x;
    const int lane = tid & 31;
    const int wid  = tid >> 5;
    const int rank = blockIdx.x & (CLSZ - 1);
    const int cl   = blockIdx.x >> 2;

    uint2*    wf = (uint2*)(smem_u + WF_W);
    uint32_t* af = smem_u + AF_W;

    // ---- one-time: W chunk [256 x 384] -> bf16 B-fragment order ----
    // wf[(nt*NKT + kt)*32 + l]: nloc = nt*8 + (l>>2); local row nloc in [0,256):
    //   gate = nloc>>6, unit = nloc&63; global row R = gate*256 + rank*64 + unit.
    for (int idx = tid; idx < NNT * NKT * 32; idx += NTHR) {
        int l  = idx & 31;
        int kt = (idx >> 5) % NKT;
        int nt = idx / (32 * NKT);
        int n  = nt * 8 + (l >> 2);
        int R  = ((n >> 6) << 8) + rank * 64 + (n & 63);
        int ka = kt * 16 + (l & 3) * 2;
        int kb = ka + 8;
        float w00 = (ka     < HDIM) ? Whh[R * HDIM + ka]     : Wih[R * EDIM + ka - HDIM];
        float w01 = (ka + 1 < HDIM) ? Whh[R * HDIM + ka + 1] : Wih[R * EDIM + ka + 1 - HDIM];
        float w10 = (kb     < HDIM) ? Whh[R * HDIM + kb]     : Wih[R * EDIM + kb - HDIM];
        float w11 = (kb + 1 < HDIM) ? Whh[R * HDIM + kb + 1] : Wih[R * EDIM + kb + 1 - HDIM];
        wf[idx] = make_uint2(packbf(w00, w01), packbf(w10, w11));
    }

    // ---- per-thread cell constants ----
    // Thread owns units u0,u0+1 (u0 = 8*wid + 2*(lane&3)) for batches b and b+8.
    const int u0 = 8 * wid + ((lane & 3) << 1);
    const int b  = lane >> 2;
    float bias0[4], bias1[4];
    #pragma unroll
    for (int g = 0; g < 4; ++g) {
        int R0 = (g << 8) + rank * 64 + u0;
        bias0[g] = bih[R0] + bhh[R0];
        bias1[g] = bih[R0 + 1] + bhh[R0 + 1];
    }
    const int kcol = rank * 64 + u0;                    // K-position of owned units
    const uint32_t pushB0 = (uint32_t)afrag_word(b,     kcol) * 4;
    const uint32_t pushB1 = (uint32_t)afrag_word(b + 8, kcol) * 4;
    const uint32_t af_base = smem_u32(af);
    uint32_t remAF[CLSZ];
    #pragma unroll
    for (uint32_t r = 0; r < CLSZ; ++r) remAF[r] = mapa32(af_base, r);
    float c00 = 0.0f, c01 = 0.0f, c10 = 0.0f, c11 = 0.0f;

    // ---- staging constants: thread stages 4 packed x words (one batch row) ----
    // pair index p = (tid&15)*4 + s, batch sb = tid>>4; cols = 256 + 2p (emb col 2p)
    const int sb = tid >> 4;
    const int sp = (tid & 15) * 4;
    int sword[4];
    #pragma unroll
    for (int s = 0; s < 4; ++s) sword[s] = afrag_word(sb, 256 + 2 * (sp + s));

    // ---- prologue: zero both A buffers (h part), stage x(0) into buf0 ----
    for (int w = tid; w < 2 * AF_STRIDE_W; w += NTHR) af[w] = 0u;
    __syncthreads();
    {
        int tok = __ldg(&inputs[cl * BC + sb]);
        const float4* er = (const float4*)&emb[tok * EDIM + 2 * sp];
        float4 e0 = __ldg(er), e1 = __ldg(er + 1);
        af[sword[0]] = packbf(e0.x, e0.y);
        af[sword[1]] = packbf(e0.z, e0.w);
        af[sword[2]] = packbf(e1.x, e1.y);
        af[sword[3]] = packbf(e1.z, e1.w);
    }
    carrive();
    cwait();

    // ---- scan ----
    for (int t = 0; t < T_STEPS; ++t) {
        const uint32_t* cur = af + (t & 1) * AF_STRIDE_W;
        uint32_t*       nxt = af + ((t + 1) & 1) * AF_STRIDE_W;

        // issue x(t+1) loads early (latency hidden under the k-loop)
        float4 e0, e1;
        bool do_stage = (t + 1 < T_STEPS);
        if (do_stage) {
            int tok = __ldg(&inputs[(t + 1) * BATCH + cl * BC + sb]);
            const float4* er = (const float4*)&emb[tok * EDIM + 2 * sp];
            e0 = __ldg(er);
            e1 = __ldg(er + 1);
        }

        // mma: warp wid handles n-tiles {wid + 8g}; acc[g] = gate g of owned cells
        float acc[4][4];
        #pragma unroll
        for (int g = 0; g < 4; ++g) {
            acc[g][0] = bias0[g]; acc[g][1] = bias1[g];
            acc[g][2] = bias0[g]; acc[g][3] = bias1[g];
        }
        #pragma unroll
        for (int kt = 0; kt < NKT; ++kt) {
            uint4 a = *(const uint4*)(cur + (kt * 32 + lane) * 4);
            #pragma unroll
            for (int g = 0; g < 4; ++g) {
                uint2 bf = wf[((wid + 8 * g) * NKT + kt) * 32 + lane];
                mma16816(acc[g], a.x, a.y, a.z, a.w, bf.x, bf.y);
            }
        }

        // store x(t+1) (local; must complete before arrive)
        if (do_stage) {
            nxt[sword[0]] = packbf(e0.x, e0.y);
            nxt[sword[1]] = packbf(e0.z, e0.w);
            nxt[sword[2]] = packbf(e1.x, e1.y);
            nxt[sword[3]] = packbf(e1.z, e1.w);
        }

        // LSTM cell update, all in registers
        float i0 = sigf(acc[0][0]), i1 = sigf(acc[0][1]), i2 = sigf(acc[0][2]), i3 = sigf(acc[0][3]);
        float f0 = sigf(acc[1][0]), f1 = sigf(acc[1][1]), f2 = sigf(acc[1][2]), f3 = sigf(acc[1][3]);
        float g0 = tanha(acc[2][0]), g1 = tanha(acc[2][1]), g2 = tanha(acc[2][2]), g3 = tanha(acc[2][3]);
        float o0 = sigf(acc[3][0]), o1 = sigf(acc[3][1]), o2 = sigf(acc[3][2]), o3 = sigf(acc[3][3]);
        c00 = f0 * c00 + i0 * g0;
        c01 = f1 * c01 + i1 * g1;
        c10 = f2 * c10 + i2 * g2;
        c11 = f3 * c11 + i3 * g3;
        float h00 = o0 * tanha(c00);
        float h01 = o1 * tanha(c01);
        float h10 = o2 * tanha(c10);
        float h11 = o3 * tanha(c11);

        // push h(t+1) to all 4 CTAs' next buffer
        uint32_t w0 = packbf(h00, h01);
        uint32_t w1 = packbf(h10, h11);
        uint32_t boff = (uint32_t)(((t + 1) & 1) * (AF_STRIDE_W * 4));
        #pragma unroll
        for (uint32_t r = 0; r < CLSZ; ++r) {
            stc32(remAF[r] + boff + pushB0, w0);
            stc32(remAF[r] + boff + pushB1, w1);
        }

        carrive();
        cwait();
    }

    // ---- head: h_T (= h(2048)) sits in buffer 0 fragment layout, full 256 cols ----
    if (rank == 0 && tid < BC) {
        float s = __ldg(bout);
        int bb = tid;
        float accv = 0.0f;
        #pragma unroll 8
        for (int j = 0; j < HDIM; j += 2) {
            uint32_t u = af[afrag_word(bb, j)];
            float lo = __uint_as_float(u << 16);
            float hi = __uint_as_float(u & 0xFFFF0000u);
            accv += lo * __ldg(&Wout[j]) + hi * __ldg(&Wout[j + 1]);
        }
        out[cl * BC + bb] = sigf(s + accv);
    }

    // keep cluster alive until everyone is done touching peer smem
    carrive();
    cwait();
}

extern "C" void kernel_launch(void* const* d_in, const int* in_sizes, int n_in,
                              void* d_out, int out_size)
{
    (void)in_sizes; (void)n_in; (void)out_size;
    cudaFuncSetAttribute(lstm_kernel, cudaFuncAttributeMaxDynamicSharedMemorySize,
                         SMEM_WORDS * 4);
    lstm_kernel<<<16 * CLSZ, NTHR, SMEM_WORDS * 4>>>(
        (const int*)d_in[0], (const float*)d_in[1], (const float*)d_in[2],
        (const float*)d_in[3], (const float*)d_in[4], (const float*)d_in[5],
        (const float*)d_in[6], (const float*)d_in[7], (float*)d_out);
}

// round 6
// speedup vs baseline: 7.8147x; 1.5182x over previous
#include <cuda_runtime.h>
#include <cuda_bf16.h>
#include <cstdint>

// Persistent 4-CTA-cluster LSTM scan, bf16 m16n8k16 HMMA.
//   - W recurrent part (K=[0,256), 16 k-tiles) lives in REGISTERS (128 regs/thr)
//   - W input part (K=[256,384), 8 k-tiles) lives in smem fragments
//   - register-resident gates (gate-aligned n-tile assignment, c in regs)
//   - DSMEM h exchange (st.shared::cluster.u64), double-buffered A fragments
//   - split cluster barrier: x-part GEMM of step t+1 executes between
//     arrive and wait, hiding barrier latency.
// T=2048, B=256, E=128, H=256. 16 clusters x 4 CTAs. CTA rank r owns hidden
// units [64r,64r+64); cluster cl owns batch [16cl,16cl+16).

#define T_STEPS 2048
#define BATCH   256
#define EDIM    128
#define HDIM    256
#define CLSZ    4
#define BC      16
#define NTHR    256

// smem word map
#define WF_W        0        // x-part W frags: 32nt x 8kt x 32 lanes uint2 = 16384 words
#define AF_W        16384    // A fragments: 2 buffers x 3072 words
#define AF_STRIDE_W 3072
#define SMEM_WORDS  22528    // 90112 bytes

extern __shared__ uint32_t smem_u[];

__device__ __forceinline__ uint32_t packbf(float lo, float hi) {
    uint32_t u;
    asm("cvt.rn.bf16x2.f32 %0, %1, %2;" : "=r"(u) : "f"(hi), "f"(lo));
    return u;
}
__device__ __forceinline__ float tanha(float x) {
    float y;
    asm("tanh.approx.f32 %0, %1;" : "=f"(y) : "f"(x));
    return y;
}
__device__ __forceinline__ float sigf(float x) { return fmaf(0.5f, tanha(0.5f * x), 0.5f); }
__device__ __forceinline__ void carrive() {
    asm volatile("barrier.cluster.arrive.aligned;" ::: "memory");
}
__device__ __forceinline__ void cwait() {
    asm volatile("barrier.cluster.wait.aligned;" ::: "memory");
}
__device__ __forceinline__ uint32_t smem_u32(const void* p) {
    uint32_t a;
    asm("{ .reg .u64 t; cvta.to.shared.u64 t, %1; cvt.u32.u64 %0, t; }" : "=r"(a) : "l"(p));
    return a;
}
__device__ __forceinline__ uint32_t mapa32(uint32_t a, uint32_t r) {
    uint32_t d;
    asm("mapa.shared::cluster.u32 %0, %1, %2;" : "=r"(d) : "r"(a), "r"(r));
    return d;
}
__device__ __forceinline__ void stc64(uint32_t a, uint32_t lo, uint32_t hi) {
    asm volatile("{ .reg .b64 v; mov.b64 v, {%1,%2}; st.shared::cluster.u64 [%0], v; }"
                 :: "r"(a), "r"(lo), "r"(hi) : "memory");
}
__device__ __forceinline__ void mma16816(float d[4], uint32_t a0, uint32_t a1, uint32_t a2,
                                         uint32_t a3, uint32_t b0, uint32_t b1) {
    asm volatile(
        "mma.sync.aligned.m16n8k16.row.col.f32.bf16.bf16.f32 "
        "{%0,%1,%2,%3},{%4,%5,%6,%7},{%8,%9},{%0,%1,%2,%3};"
        : "+f"(d[0]), "+f"(d[1]), "+f"(d[2]), "+f"(d[3])
        : "r"(a0), "r"(a1), "r"(a2), "r"(a3), "r"(b0), "r"(b1));
}
// word offset (within one A buffer) of packed pair holding A[row=b][col,col+1], col even
__device__ __forceinline__ int afrag_word(int b, int col) {
    int kt = col >> 4, kk = col & 15;
    int t3 = (kk >> 1) & 3;
    int r  = ((b >> 3) & 1) | (((kk >> 3) & 1) << 1);
    int ln = (b & 7) * 4 + t3;
    return (kt * 32 + ln) * 4 + r;
}

__global__ void __cluster_dims__(CLSZ, 1, 1) __launch_bounds__(NTHR, 1)
lstm_kernel(const int* __restrict__ inputs, const float* __restrict__ emb,
            const float* __restrict__ Wih, const float* __restrict__ Whh,
            const float* __restrict__ bih, const float* __restrict__ bhh,
            const float* __restrict__ Wout, const float* __restrict__ bout,
            float* __restrict__ out)
{
    const int tid  = threadIdx.x;
    const int lane = tid & 31;
    const int wid  = tid >> 5;
    const int rank = blockIdx.x & (CLSZ - 1);
    const int cl   = blockIdx.x >> 2;

    uint2*    wf = (uint2*)(smem_u + WF_W);
    uint32_t* af = smem_u + AF_W;

    // ---- one-time: x-part W (K = 256..383) -> smem bf16 B-fragment order ----
    // wf[(nt*8 + ktx)*32 + l]; nloc = nt*8 + (l>>2); R = (nloc>>6)*256 + rank*64 + (nloc&63)
    for (int idx = tid; idx < 32 * 8 * 32; idx += NTHR) {
        int l   = idx & 31;
        int ktx = (idx >> 5) & 7;
        int nt  = idx >> 8;
        int n   = nt * 8 + (l >> 2);
        int R   = ((n >> 6) << 8) + rank * 64 + (n & 63);
        int ka  = ktx * 16 + (l & 3) * 2;          // column in E (all from Wih)
        wf[idx] = make_uint2(packbf(Wih[R * EDIM + ka],     Wih[R * EDIM + ka + 1]),
                             packbf(Wih[R * EDIM + ka + 8], Wih[R * EDIM + ka + 8 + 1]));
    }

    // ---- one-time: h-part W (K = 0..255) -> REGISTERS ----
    // wreg[kt*4+g] is the B fragment for n-tile (wid+8g), k-tile kt.
    uint2 wreg[64];
    {
        const int nbase = rank * 64 + wid * 8 + (lane >> 2);
        #pragma unroll
        for (int kt = 0; kt < 16; ++kt) {
            int ka = kt * 16 + (lane & 3) * 2;
            #pragma unroll
            for (int g = 0; g < 4; ++g) {
                int R = (g << 8) + nbase;
                wreg[kt * 4 + g] =
                    make_uint2(packbf(Whh[R * HDIM + ka],     Whh[R * HDIM + ka + 1]),
                               packbf(Whh[R * HDIM + ka + 8], Whh[R * HDIM + ka + 8 + 1]));
            }
        }
    }

    // ---- per-thread cell constants ----
    // Thread owns units u0,u0+1 (u0 = 8*wid + 2*(lane&3)) for batches b and b+8.
    const int u0 = 8 * wid + ((lane & 3) << 1);
    const int b  = lane >> 2;
    float bias0[4], bias1[4];
    #pragma unroll
    for (int g = 0; g < 4; ++g) {
        int R0 = (g << 8) + rank * 64 + u0;
        bias0[g] = bih[R0] + bhh[R0];
        bias1[g] = bih[R0 + 1] + bhh[R0 + 1];
    }
    const int kcol = rank * 64 + u0;
    const uint32_t pushB = (uint32_t)afrag_word(b, kcol) * 4;   // b+8 word is +4 bytes
    const uint32_t af_base = smem_u32(af);
    uint32_t remAF[CLSZ];
    #pragma unroll
    for (uint32_t r = 0; r < CLSZ; ++r) remAF[r] = mapa32(af_base, r);
    float c00 = 0.0f, c01 = 0.0f, c10 = 0.0f, c11 = 0.0f;

    // ---- staging constants: thread stages 4 packed x words (one batch row) ----
    const int sb = tid >> 4;
    const int sp = (tid & 15) * 4;
    int sword[4];
    #pragma unroll
    for (int s = 0; s < 4; ++s) sword[s] = afrag_word(sb, 256 + 2 * (sp + s));

    // ---- prologue: zero both A buffers, stage x(0) into buf0 ----
    for (int w = tid; w < 2 * AF_STRIDE_W; w += NTHR) af[w] = 0u;
    __syncthreads();
    {
        int tok = __ldg(&inputs[cl * BC + sb]);
        const float4* er = (const float4*)&emb[tok * EDIM + 2 * sp];
        float4 e0 = __ldg(er), e1 = __ldg(er + 1);
        af[sword[0]] = packbf(e0.x, e0.y);
        af[sword[1]] = packbf(e0.z, e0.w);
        af[sword[2]] = packbf(e1.x, e1.y);
        af[sword[3]] = packbf(e1.z, e1.w);
    }
    __syncthreads();

    // x-part accumulation for step 0 (local data only)
    float acc[4][4];
    #pragma unroll
    for (int g = 0; g < 4; ++g) {
        acc[g][0] = bias0[g]; acc[g][1] = bias1[g];
        acc[g][2] = bias0[g]; acc[g][3] = bias1[g];
    }
    #pragma unroll
    for (int ktx = 0; ktx < 8; ++ktx) {
        uint4 a = *(const uint4*)(af + ((16 + ktx) * 32 + lane) * 4);
        #pragma unroll
        for (int g = 0; g < 4; ++g) {
            uint2 bf = wf[((wid + 8 * g) * 8 + ktx) * 32 + lane];
            mma16816(acc[g], a.x, a.y, a.z, a.w, bf.x, bf.y);
        }
    }
    carrive();
    cwait();   // all CTAs zeroed + staged before any pushes land

    // ---- scan ----
    for (int t = 0; t < T_STEPS; ++t) {
        const uint32_t* cur = af + (t & 1) * AF_STRIDE_W;
        uint32_t*       nxt = af + ((t + 1) & 1) * AF_STRIDE_W;
        const bool more = (t + 1 < T_STEPS);

        // issue x(t+1) loads early
        float4 e0, e1;
        if (more) {
            int tok = __ldg(&inputs[(t + 1) * BATCH + cl * BC + sb]);
            const float4* er = (const float4*)&emb[tok * EDIM + 2 * sp];
            e0 = __ldg(er);
            e1 = __ldg(er + 1);
        }

        // h-part mma on cur: W from registers (16 k-tiles)
        #pragma unroll
        for (int kt = 0; kt < 16; ++kt) {
            uint4 a = *(const uint4*)(cur + (kt * 32 + lane) * 4);
            #pragma unroll
            for (int g = 0; g < 4; ++g) {
                uint2 bf = wreg[kt * 4 + g];
                mma16816(acc[g], a.x, a.y, a.z, a.w, bf.x, bf.y);
            }
        }

        // LSTM cell update, all in registers
        float i0 = sigf(acc[0][0]), i1 = sigf(acc[0][1]), i2 = sigf(acc[0][2]), i3 = sigf(acc[0][3]);
        float f0 = sigf(acc[1][0]), f1 = sigf(acc[1][1]), f2 = sigf(acc[1][2]), f3 = sigf(acc[1][3]);
        float g0 = tanha(acc[2][0]), g1 = tanha(acc[2][1]), g2 = tanha(acc[2][2]), g3 = tanha(acc[2][3]);
        float o0 = sigf(acc[3][0]), o1 = sigf(acc[3][1]), o2 = sigf(acc[3][2]), o3 = sigf(acc[3][3]);
        c00 = f0 * c00 + i0 * g0;
        c01 = f1 * c01 + i1 * g1;
        c10 = f2 * c10 + i2 * g2;
        c11 = f3 * c11 + i3 * g3;
        float h00 = o0 * tanha(c00);
        float h01 = o1 * tanha(c01);
        float h10 = o2 * tanha(c10);
        float h11 = o3 * tanha(c11);

        // push h(t+1) to all 4 CTAs' next buffer (one u64 per destination)
        uint32_t w0 = packbf(h00, h01);        // batch b
        uint32_t w1 = packbf(h10, h11);        // batch b+8 (adjacent word)
        uint32_t boff = (uint32_t)(((t + 1) & 1) * (AF_STRIDE_W * 4)) + pushB;
        #pragma unroll
        for (uint32_t r = 0; r < CLSZ; ++r) stc64(remAF[r] + boff, w0, w1);

        // stage x(t+1) locally
        if (more) {
            nxt[sword[0]] = packbf(e0.x, e0.y);
            nxt[sword[1]] = packbf(e0.z, e0.w);
            nxt[sword[2]] = packbf(e1.x, e1.y);
            nxt[sword[3]] = packbf(e1.z, e1.w);
        }

        __syncthreads();   // local x staging visible to all warps before x-part mma
        carrive();         // release our pushes (gen t+1)

        // x-part mma for step t+1 on nxt — local data only, hides barrier latency
        #pragma unroll
        for (int g = 0; g < 4; ++g) {
            acc[g][0] = bias0[g]; acc[g][1] = bias1[g];
            acc[g][2] = bias0[g]; acc[g][3] = bias1[g];
        }
        if (more) {
            #pragma unroll
            for (int ktx = 0; ktx < 8; ++ktx) {
                uint4 a = *(const uint4*)(nxt + ((16 + ktx) * 32 + lane) * 4);
                #pragma unroll
                for (int g = 0; g < 4; ++g) {
                    uint2 bf = wf[((wid + 8 * g) * 8 + ktx) * 32 + lane];
                    mma16816(acc[g], a.x, a.y, a.z, a.w, bf.x, bf.y);
                }
            }
        }

        cwait();           // acquire peers' pushes (gen t+1)
    }

    // ---- head: h_T (= h(2048)) in buffer 0, fragment layout, full 256 cols ----
    if (rank == 0 && tid < BC) {
        float s = __ldg(bout);
        int bb = tid;
        float accv = 0.0f;
        #pragma unroll 8
        for (int j = 0; j < HDIM; j += 2) {
            uint32_t u = af[afrag_word(bb, j)];
            float lo = __uint_as_float(u << 16);
            float hi = __uint_as_float(u & 0xFFFF0000u);
            accv += lo * __ldg(&Wout[j]) + hi * __ldg(&Wout[j + 1]);
        }
        out[cl * BC + bb] = sigf(s + accv);
    }

    // keep cluster alive until everyone is done touching peer smem
    carrive();
    cwait();
}

extern "C" void kernel_launch(void* const* d_in, const int* in_sizes, int n_in,
                              void* d_out, int out_size)
{
    (void)in_sizes; (void)n_in; (void)out_size;
    cudaFuncSetAttribute(lstm_kernel, cudaFuncAttributeMaxDynamicSharedMemorySize,
                         SMEM_WORDS * 4);
    lstm_kernel<<<16 * CLSZ, NTHR, SMEM_WORDS * 4>>>(
        (const int*)d_in[0], (const float*)d_in[1], (const float*)d_in[2],
        (const float*)d_in[3], (const float*)d_in[4], (const float*)d_in[5],
        (const float*)d_in[6], (const float*)d_in[7], (float*)d_out);
}

// round 7
// speedup vs baseline: 9.2279x; 1.1808x over previous
#include <cuda_runtime.h>
#include <cuda_bf16.h>
#include <cstdint>

// Persistent 4-CTA-cluster LSTM scan, bf16 m16n8k16 HMMA.
//   - W recurrent part kt 0..11 in REGISTERS (96 regs), kt 12..15 + x-part
//     kt 16..23 in smem fragments
//   - register-resident gates (gate-aligned n-tiles), split accumulators
//     (accA/accB) to halve the HMMA accumulate chain
//   - h exchange: st.async.shared::cluster with mbarrier complete_tx (no
//     per-step cluster barrier; two parity barriers, expect_tx re-arm)
//   - x-part GEMM of step t+1 runs while peers' st.async are in flight
// T=2048, B=256, E=128, H=256. 16 clusters x 4 CTAs = 64 CTAs.
// CTA rank r owns hidden units [64r,64r+64); cluster cl owns batch [16cl,16cl+16).

#define T_STEPS 2048
#define BATCH   256
#define EDIM    128
#define HDIM    256
#define CLSZ    4
#define BC      16
#define NTHR    256

// smem word map
#define WF_W        0        // smem W frags: 32nt x 12kt x 32 lanes uint2 = 24576 words
#define AF_W        24576    // A fragments: 2 buffers x 3072 words
#define AF_STRIDE_W 3072
#define MB_W        30720    // full[0] @30720, full[1] @30722 (8B each)
#define SMEM_WORDS  30728    // 122912 bytes

#define TX_BYTES (CLSZ * NTHR * 8)   // 8192: 4 source CTAs x 256 threads x 8B

extern __shared__ uint32_t smem_u[];

__device__ __forceinline__ uint32_t packbf(float lo, float hi) {
    uint32_t u;
    asm("cvt.rn.bf16x2.f32 %0, %1, %2;" : "=r"(u) : "f"(hi), "f"(lo));
    return u;
}
__device__ __forceinline__ float tanha(float x) {
    float y;
    asm("tanh.approx.f32 %0, %1;" : "=f"(y) : "f"(x));
    return y;
}
__device__ __forceinline__ float sigf(float x) { return fmaf(0.5f, tanha(0.5f * x), 0.5f); }
__device__ __forceinline__ void csync() {
    asm volatile("barrier.cluster.arrive.aligned;" ::: "memory");
    asm volatile("barrier.cluster.wait.aligned;" ::: "memory");
}
__device__ __forceinline__ uint32_t smem_u32(const void* p) {
    uint32_t a;
    asm("{ .reg .u64 t; cvta.to.shared.u64 t, %1; cvt.u32.u64 %0, t; }" : "=r"(a) : "l"(p));
    return a;
}
__device__ __forceinline__ uint32_t mapa32(uint32_t a, uint32_t r) {
    uint32_t d;
    asm("mapa.shared::cluster.u32 %0, %1, %2;" : "=r"(d) : "r"(a), "r"(r));
    return d;
}
__device__ __forceinline__ void mbar_init(uint32_t a, uint32_t n) {
    asm volatile("mbarrier.init.shared.b64 [%0], %1;" :: "r"(a), "r"(n) : "memory");
}
__device__ __forceinline__ void mbar_arm(uint32_t a, uint32_t tx) {
    asm volatile("mbarrier.arrive.expect_tx.shared.b64 _, [%0], %1;" :: "r"(a), "r"(tx) : "memory");
}
__device__ __forceinline__ void mbar_wait(uint32_t a, uint32_t phase) {
    uint32_t done;
    asm volatile(
        "{\n\t.reg .pred p;\n\t"
        "mbarrier.try_wait.parity.acquire.cluster.shared::cta.b64 p, [%1], %2;\n\t"
        "selp.b32 %0, 1, 0, p;\n\t}"
        : "=r"(done) : "r"(a), "r"(phase) : "memory");
    if (!done) {
        asm volatile(
            "{\n\t.reg .pred P1;\n\t"
            "W_%=:\n\t"
            "mbarrier.try_wait.parity.acquire.cluster.shared::cta.b64 P1, [%0], %1, 0x989680;\n\t"
            "@P1 bra.uni D_%=;\n\t"
            "bra.uni W_%=;\n\t"
            "D_%=:\n\t}"
            :: "r"(a), "r"(phase) : "memory");
    }
}
// st.async: remote smem store with mbarrier tx-completion at the DEST CTA
__device__ __forceinline__ void st_async64(uint32_t daddr, uint32_t dmbar,
                                           uint32_t lo, uint32_t hi) {
    asm volatile(
        "{\n\t.reg .b64 v;\n\tmov.b64 v, {%2, %3};\n\t"
        "st.async.weak.shared::cluster.mbarrier::complete_tx::bytes.b64 [%0], v, [%1];\n\t}"
        :: "r"(daddr), "r"(dmbar), "r"(lo), "r"(hi) : "memory");
}
__device__ __forceinline__ void mma16816(float d[4], uint32_t a0, uint32_t a1, uint32_t a2,
                                         uint32_t a3, uint32_t b0, uint32_t b1) {
    asm volatile(
        "mma.sync.aligned.m16n8k16.row.col.f32.bf16.bf16.f32 "
        "{%0,%1,%2,%3},{%4,%5,%6,%7},{%8,%9},{%0,%1,%2,%3};"
        : "+f"(d[0]), "+f"(d[1]), "+f"(d[2]), "+f"(d[3])
        : "r"(a0), "r"(a1), "r"(a2), "r"(a3), "r"(b0), "r"(b1));
}
// word offset (within one A buffer) of packed pair holding A[row=b][col,col+1], col even
__device__ __forceinline__ int afrag_word(int b, int col) {
    int kt = col >> 4, kk = col & 15;
    int t3 = (kk >> 1) & 3;
    int r  = ((b >> 3) & 1) | (((kk >> 3) & 1) << 1);
    int ln = (b & 7) * 4 + t3;
    return (kt * 32 + ln) * 4 + r;
}

__global__ void __cluster_dims__(CLSZ, 1, 1) __launch_bounds__(NTHR, 1)
lstm_kernel(const int* __restrict__ inputs, const float* __restrict__ emb,
            const float* __restrict__ Wih, const float* __restrict__ Whh,
            const float* __restrict__ bih, const float* __restrict__ bhh,
            const float* __restrict__ Wout, const float* __restrict__ bout,
            float* __restrict__ out)
{
    const int tid  = threadIdx.x;
    const int lane = tid & 31;
    const int wid  = tid >> 5;
    const int rank = blockIdx.x & (CLSZ - 1);
    const int cl   = blockIdx.x >> 2;

    uint2*    wf = (uint2*)(smem_u + WF_W);
    uint32_t* af = smem_u + AF_W;

    const uint32_t smem_base = smem_u32(smem_u);
    const uint32_t af_base   = smem_base + AF_W * 4;
    const uint32_t mb0       = smem_base + MB_W * 4;
    const uint32_t mb1       = mb0 + 8;

    // ---- one-time: smem W frags, skt 0..11 <-> global kt 12..23 ----
    for (int idx = tid; idx < 32 * 12 * 32; idx += NTHR) {
        int l   = idx & 31;
        int skt = (idx >> 5) % 12;
        int nt  = idx / (32 * 12);
        int n   = nt * 8 + (l >> 2);
        int R   = ((n >> 6) << 8) + rank * 64 + (n & 63);
        int ka  = (12 + skt) * 16 + (l & 3) * 2;
        int kb  = ka + 8;
        float w00 = (ka     < HDIM) ? Whh[R * HDIM + ka]     : Wih[R * EDIM + ka - HDIM];
        float w01 = (ka + 1 < HDIM) ? Whh[R * HDIM + ka + 1] : Wih[R * EDIM + ka + 1 - HDIM];
        float w10 = (kb     < HDIM) ? Whh[R * HDIM + kb]     : Wih[R * EDIM + kb - HDIM];
        float w11 = (kb + 1 < HDIM) ? Whh[R * HDIM + kb + 1] : Wih[R * EDIM + kb + 1 - HDIM];
        wf[idx] = make_uint2(packbf(w00, w01), packbf(w10, w11));
    }

    // ---- one-time: h-part W kt 0..11 -> registers ----
    uint2 wreg[48];
    {
        const int nbase = rank * 64 + wid * 8 + (lane >> 2);
        #pragma unroll
        for (int kt = 0; kt < 12; ++kt) {
            int ka = kt * 16 + (lane & 3) * 2;
            #pragma unroll
            for (int g = 0; g < 4; ++g) {
                int R = (g << 8) + nbase;
                wreg[kt * 4 + g] =
                    make_uint2(packbf(Whh[R * HDIM + ka],     Whh[R * HDIM + ka + 1]),
                               packbf(Whh[R * HDIM + ka + 8], Whh[R * HDIM + ka + 8 + 1]));
            }
        }
    }

    // ---- per-thread cell constants ----
    const int u0 = 8 * wid + ((lane & 3) << 1);
    const int b  = lane >> 2;
    float bias0[4], bias1[4];
    #pragma unroll
    for (int g = 0; g < 4; ++g) {
        int R0 = (g << 8) + rank * 64 + u0;
        bias0[g] = bih[R0] + bhh[R0];
        bias1[g] = bih[R0 + 1] + bhh[R0 + 1];
    }
    const int kcol = rank * 64 + u0;
    const uint32_t pushB = (uint32_t)afrag_word(b, kcol) * 4;  // b+8 word = +4 bytes (8B aligned)
    uint32_t remAF[CLSZ], remMB0[CLSZ], remMB1[CLSZ];
    #pragma unroll
    for (uint32_t r = 0; r < CLSZ; ++r) {
        remAF[r]  = mapa32(af_base, r);
        remMB0[r] = mapa32(mb0, r);
        remMB1[r] = mapa32(mb1, r);
    }
    float c00 = 0.0f, c01 = 0.0f, c10 = 0.0f, c11 = 0.0f;

    // ---- staging constants ----
    const int sb = tid >> 4;
    const int sp = (tid & 15) * 4;
    int sword[4];
    #pragma unroll
    for (int s = 0; s < 4; ++s) sword[s] = afrag_word(sb, 256 + 2 * (sp + s));

    // ---- mbarrier init + prologue ----
    if (tid == 0) {
        mbar_init(mb0, 1);
        mbar_init(mb1, 1);
        mbar_arm(mb1, TX_BYTES);        // gen 1
    }
    for (int w = tid; w < 2 * AF_STRIDE_W; w += NTHR) af[w] = 0u;
    __syncthreads();
    {
        int tok = __ldg(&inputs[cl * BC + sb]);
        const float4* er = (const float4*)&emb[tok * EDIM + 2 * sp];
        float4 e0 = __ldg(er), e1 = __ldg(er + 1);
        af[sword[0]] = packbf(e0.x, e0.y);
        af[sword[1]] = packbf(e0.z, e0.w);
        af[sword[2]] = packbf(e1.x, e1.y);
        af[sword[3]] = packbf(e1.z, e1.w);
    }
    __syncthreads();
    csync();   // all CTAs: barriers armed + buffers zeroed before any st.async

    // x-part accumulation for step 0
    float accA[4][4], accB[4][4];
    #pragma unroll
    for (int g = 0; g < 4; ++g) {
        accA[g][0] = bias0[g]; accA[g][1] = bias1[g];
        accA[g][2] = bias0[g]; accA[g][3] = bias1[g];
        accB[g][0] = 0.f; accB[g][1] = 0.f; accB[g][2] = 0.f; accB[g][3] = 0.f;
    }
    #pragma unroll
    for (int j = 0; j < 8; ++j) {
        uint4 a = *(const uint4*)(af + ((16 + j) * 32 + lane) * 4);
        #pragma unroll
        for (int g = 0; g < 4; ++g) {
            uint2 bf = wf[((wid + 8 * g) * 12 + 4 + j) * 32 + lane];
            mma16816(accB[g], a.x, a.y, a.z, a.w, bf.x, bf.y);
        }
    }

    uint32_t ph0 = 0, ph1 = 0;

    // ---- scan: two steps per iteration (compile-time parities) ----
    #define STEP_BODY(T_, PAR_, MBW_, PHW_, REMMB_)                                        \
    {                                                                                      \
        const int t = (T_);                                                                \
        if (t > 0) { mbar_wait(MBW_, PHW_); PHW_ ^= 1; }                                   \
        if (tid == 0) mbar_arm(MBW_, TX_BYTES);     /* re-arm for gen t+2 */               \
        const uint32_t* cur = af + (PAR_) * AF_STRIDE_W;                                   \
        uint32_t*       nxt = af + (1 - (PAR_)) * AF_STRIDE_W;                             \
        const bool more = (t + 1 < T_STEPS);                                               \
        float4 e0, e1;                                                                     \
        if (more) {                                                                        \
            int tok = __ldg(&inputs[(t + 1) * BATCH + cl * BC + sb]);                      \
            const float4* er = (const float4*)&emb[tok * EDIM + 2 * sp];                   \
            e0 = __ldg(er); e1 = __ldg(er + 1);                                            \
        }                                                                                  \
        /* h-part mma: kt 0..5 -> accA, 6..11 -> accB (regs); skt 0..1 -> accA,            \
           skt 2..3 -> accB (smem) */                                                      \
        _Pragma("unroll")                                                                  \
        for (int kt = 0; kt < 6; ++kt) {                                                   \
            uint4 a = *(const uint4*)(cur + (kt * 32 + lane) * 4);                         \
            _Pragma("unroll")                                                              \
            for (int g = 0; g < 4; ++g) {                                                  \
                uint2 bf = wreg[kt * 4 + g];                                               \
                mma16816(accA[g], a.x, a.y, a.z, a.w, bf.x, bf.y);                         \
            }                                                                              \
        }                                                                                  \
        _Pragma("unroll")                                                                  \
        for (int kt = 6; kt < 12; ++kt) {                                                  \
            uint4 a = *(const uint4*)(cur + (kt * 32 + lane) * 4);                         \
            _Pragma("unroll")                                                              \
            for (int g = 0; g < 4; ++g) {                                                  \
                uint2 bf = wreg[kt * 4 + g];                                               \
                mma16816(accB[g], a.x, a.y, a.z, a.w, bf.x, bf.y);                         \
            }                                                                              \
        }                                                                                  \
        _Pragma("unroll")                                                                  \
        for (int skt = 0; skt < 4; ++skt) {                                                \
            uint4 a = *(const uint4*)(cur + ((12 + skt) * 32 + lane) * 4);                 \
            _Pragma("unroll")                                                              \
            for (int g = 0; g < 4; ++g) {                                                  \
                uint2 bf = wf[((wid + 8 * g) * 12 + skt) * 32 + lane];                     \
                if (skt < 2) mma16816(accA[g], a.x, a.y, a.z, a.w, bf.x, bf.y);            \
                else         mma16816(accB[g], a.x, a.y, a.z, a.w, bf.x, bf.y);            \
            }                                                                              \
        }                                                                                  \
        /* cell update in registers */                                                     \
        float s0[4], s1[4], s2[4], s3[4];                                                  \
        _Pragma("unroll")                                                                  \
        for (int g = 0; g < 4; ++g) {                                                      \
            s0[g] = accA[g][0] + accB[g][0];                                               \
            s1[g] = accA[g][1] + accB[g][1];                                               \
            s2[g] = accA[g][2] + accB[g][2];                                               \
            s3[g] = accA[g][3] + accB[g][3];                                               \
        }                                                                                  \
        float i0 = sigf(s0[0]), i1 = sigf(s1[0]), i2 = sigf(s2[0]), i3 = sigf(s3[0]);      \
        float f0 = sigf(s0[1]), f1 = sigf(s1[1]), f2 = sigf(s2[1]), f3 = sigf(s3[1]);      \
        float g0 = tanha(s0[2]), g1 = tanha(s1[2]), g2 = tanha(s2[2]), g3 = tanha(s3[2]);  \
        float o0 = sigf(s0[3]), o1 = sigf(s1[3]), o2 = sigf(s2[3]), o3 = sigf(s3[3]);      \
        c00 = f0 * c00 + i0 * g0;                                                          \
        c01 = f1 * c01 + i1 * g1;                                                          \
        c10 = f2 * c10 + i2 * g2;                                                          \
        c11 = f3 * c11 + i3 * g3;                                                          \
        uint32_t w0 = packbf(o0 * tanha(c00), o1 * tanha(c01));                            \
        uint32_t w1 = packbf(o2 * tanha(c10), o3 * tanha(c11));                            \
        /* push h(t+1) via st.async with tx completion at dest barrier */                  \
        uint32_t boff = (uint32_t)((1 - (PAR_)) * (AF_STRIDE_W * 4)) + pushB;              \
        _Pragma("unroll")                                                                  \
        for (uint32_t r = 0; r < CLSZ; ++r)                                                \
            st_async64(remAF[r] + boff, (REMMB_)[r], w0, w1);                              \
        /* stage x(t+1) locally */                                                         \
        if (more) {                                                                        \
            nxt[sword[0]] = packbf(e0.x, e0.y);                                            \
            nxt[sword[1]] = packbf(e0.z, e0.w);                                            \
            nxt[sword[2]] = packbf(e1.x, e1.y);                                            \
            nxt[sword[3]] = packbf(e1.z, e1.w);                                            \
        }                                                                                  \
        __syncthreads();                                                                   \
        /* re-init accumulators; x-part mma for t+1 hides st.async flight */               \
        _Pragma("unroll")                                                                  \
        for (int g = 0; g < 4; ++g) {                                                      \
            accA[g][0] = bias0[g]; accA[g][1] = bias1[g];                                  \
            accA[g][2] = bias0[g]; accA[g][3] = bias1[g];                                  \
            accB[g][0] = 0.f; accB[g][1] = 0.f; accB[g][2] = 0.f; accB[g][3] = 0.f;        \
        }                                                                                  \
        if (more) {                                                                        \
            _Pragma("unroll")                                                              \
            for (int j = 0; j < 8; ++j) {                                                  \
                uint4 a = *(const uint4*)(nxt + ((16 + j) * 32 + lane) * 4);               \
                _Pragma("unroll")                                                          \
                for (int g = 0; g < 4; ++g) {                                              \
                    uint2 bf = wf[((wid + 8 * g) * 12 + 4 + j) * 32 + lane];               \
                    mma16816(accB[g], a.x, a.y, a.z, a.w, bf.x, bf.y);                     \
                }                                                                          \
            }                                                                              \
        }                                                                                  \
    }

    for (int tt = 0; tt < T_STEPS; tt += 2) {
        STEP_BODY(tt,     0, mb0, ph0, remMB1)   // even step: wait mb0, push -> mb1
        STEP_BODY(tt + 1, 1, mb1, ph1, remMB0)   // odd step:  wait mb1, push -> mb0
    }
    #undef STEP_BODY

    // ---- final: gen 2048 (parity 0) must land in every CTA before reads/exit ----
    mbar_wait(mb0, ph0);

    // head: h_T in buffer 0, fragment layout, full 256 cols
    if (rank == 0 && tid < BC) {
        float s = __ldg(bout);
        int bb = tid;
        float accv = 0.0f;
        #pragma unroll 8
        for (int j = 0; j < HDIM; j += 2) {
            uint32_t u = af[afrag_word(bb, j)];
            float lo = __uint_as_float(u << 16);
            float hi = __uint_as_float(u & 0xFFFF0000u);
            accv += lo * __ldg(&Wout[j]) + hi * __ldg(&Wout[j + 1]);
        }
        out[cl * BC + bb] = sigf(s + accv);
    }

    // keep cluster alive until all CTAs have received their final pushes
    csync();
}

extern "C" void kernel_launch(void* const* d_in, const int* in_sizes, int n_in,
                              void* d_out, int out_size)
{
    (void)in_sizes; (void)n_in; (void)out_size;
    cudaFuncSetAttribute(lstm_kernel, cudaFuncAttributeMaxDynamicSharedMemorySize,
                         SMEM_WORDS * 4);
    lstm_kernel<<<16 * CLSZ, NTHR, SMEM_WORDS * 4>>>(
        (const int*)d_in[0], (const float*)d_in[1], (const float*)d_in[2],
        (const float*)d_in[3], (const float*)d_in[4], (const float*)d_in[5],
        (const float*)d_in[6], (const float*)d_in[7], (float*)d_out);
}